// round 16
// baseline (speedup 1.0000x reference)
#include <cuda_runtime.h>
#include <cuda_fp16.h>
#include <float.h>
#include <math.h>
#include <stdint.h>

#define N_TOK 16384
#define C_DIM 1024
#define C4    (C_DIM/4)
#define K_CB  4096
#define MOMENTUM 0.99f
#define EPS 1e-6f

// ---- GEMM tiling (int8) ----
#define BTM 128
#define BTN 128
#define KCH 128
#define NCHUNK (C_DIM/KCH)            // 8
#define ROW_BYTES 144
#define TILE_BYTES (128*ROW_BYTES)    // 18432
#define STAGE_BYTES (2*TILE_BYTES)    // 36864
#define NSTAGE 2                      // 73.7KB -> 2 CTAs/SM
#define RESCUE_TAU 6.0e-3f

// ---------------- device scratch ----------------
__device__ float    g_invn[N_TOK];
__device__ float    g_ascale[N_TOK];
__device__ float    g_bscale[K_CB];
__device__ uint32_t g_feat_q[(size_t)N_TOK*C_DIM/4];
__device__ uint32_t g_cb_q[(size_t)K_CB*C_DIM/4];
__device__ float    g_c2[K_CB];
__device__ float    g_sums[(size_t)K_CB*C_DIM];
__device__ float    g_counts[K_CB];
__device__ unsigned long long g_cand[(size_t)N_TOK*128];

// ---------------- PTX helpers ----------------
__device__ __forceinline__ uint32_t s2u(const void* p) {
    uint32_t a;
    asm("{ .reg .u64 t; cvta.to.shared.u64 t, %1; cvt.u32.u64 %0, t; }" : "=r"(a) : "l"(p));
    return a;
}
#define CPA16(d, s) asm volatile("cp.async.cg.shared.global [%0], [%1], 16;" :: "r"(d), "l"(s))
#define CPA_COMMIT() asm volatile("cp.async.commit_group;" ::: "memory")
#define CPA_WAIT0()  asm volatile("cp.async.wait_group 0;" ::: "memory")
#define GRIDDEP_WAIT() asm volatile("griddepcontrol.wait;" ::: "memory")

__device__ __forceinline__ void ldsm_x4(uint32_t addr, uint32_t* r) {
    asm volatile("ldmatrix.sync.aligned.m8n8.x4.shared.b16 {%0,%1,%2,%3}, [%4];"
                 : "=r"(r[0]), "=r"(r[1]), "=r"(r[2]), "=r"(r[3]) : "r"(addr));
}
__device__ __forceinline__ void imma16832(int* c, const uint32_t* a, uint32_t b0, uint32_t b1) {
    asm volatile("mma.sync.aligned.m16n8k32.row.col.s32.s8.s8.s32 "
                 "{%0,%1,%2,%3}, {%4,%5,%6,%7}, {%8,%9}, {%0,%1,%2,%3};"
                 : "+r"(c[0]), "+r"(c[1]), "+r"(c[2]), "+r"(c[3])
                 : "r"(a[0]), "r"(a[1]), "r"(a[2]), "r"(a[3]), "r"(b0), "r"(b1));
}
__device__ __forceinline__ void red_v4(float* gaddr, float4 v) {
    asm volatile("red.global.add.v4.f32 [%0], {%1,%2,%3,%4};"
                 :: "l"(gaddr), "f"(v.x), "f"(v.y), "f"(v.z), "f"(v.w) : "memory");
}
__device__ __forceinline__ void st_v2u64(unsigned long long* gaddr,
                                         unsigned long long a, unsigned long long b) {
    asm volatile("st.global.v2.u64 [%0], {%1,%2};" :: "l"(gaddr), "l"(a), "l"(b) : "memory");
}

__device__ __forceinline__ unsigned enc_f(float f) {
    unsigned u = __float_as_uint(f);
    return (u & 0x80000000u) ? ~u : (u | 0x80000000u);
}
__device__ __forceinline__ float dec_f(unsigned u) {
    unsigned b = (u & 0x80000000u) ? (u & 0x7FFFFFFFu) : ~u;
    return __uint_as_float(b);
}
__device__ __forceinline__ float warp_sum(float v) {
#pragma unroll
    for (int o = 16; o > 0; o >>= 1) v += __shfl_xor_sync(0xffffffffu, v, o);
    return v;
}
__device__ __forceinline__ float warp_max(float v) {
#pragma unroll
    for (int o = 16; o > 0; o >>= 1) v = fmaxf(v, __shfl_xor_sync(0xffffffffu, v, o));
    return v;
}
__device__ __forceinline__ uint32_t quant_pack(float4 o, float qs) {
    int qx = __float2int_rn(o.x * qs), qy = __float2int_rn(o.y * qs);
    int qz = __float2int_rn(o.z * qs), qw = __float2int_rn(o.w * qs);
    return (qx & 0xFF) | ((qy & 0xFF) << 8) | ((qz & 0xFF) << 16) | ((qw & 0xFF) << 24);
}

// ---------------- prep: warp-per-row ----------------
__global__ void __launch_bounds__(256) prep_kernel(const float* __restrict__ hs,
                                                   const float* __restrict__ cb) {
    const int tid = threadIdx.x;
    const int wid = tid >> 5;
    const int lane = tid & 31;
    const int b = blockIdx.x;

    if (b < 2048) {
        const int row = b * 8 + wid;
        const float4* src = reinterpret_cast<const float4*>(hs) + (size_t)row * C4;
        float4 x[8];
        float ss = 0.0f, mab = 0.0f;
#pragma unroll
        for (int i = 0; i < 8; i++) {
            x[i] = src[lane + 32 * i];
            ss += x[i].x*x[i].x + x[i].y*x[i].y + x[i].z*x[i].z + x[i].w*x[i].w;
            mab = fmaxf(mab, fmaxf(fmaxf(fabsf(x[i].x), fabsf(x[i].y)),
                                   fmaxf(fabsf(x[i].z), fabsf(x[i].w))));
        }
        float nrm = sqrtf(warp_sum(ss));
        float mraw = warp_max(mab);
        float inv = 1.0f / fmaxf(nrm, EPS);
        float m = mraw * inv;
        if (lane == 0) { g_invn[row] = inv; g_ascale[row] = m * (1.0f/127.0f); }
        float qs = 127.0f / m;
        uint32_t* dst = g_feat_q + (size_t)row * 256;
#pragma unroll
        for (int i = 0; i < 8; i++) {
            float4 o = make_float4(x[i].x*inv, x[i].y*inv, x[i].z*inv, x[i].w*inv);
            dst[lane + 32 * i] = quant_pack(o, qs);
        }
    } else if (b < 2560) {
        const int k = (b - 2048) * 8 + wid;
        const float4* src = reinterpret_cast<const float4*>(cb) + (size_t)k * C4;
        float4 x[8];
        float ss = 0.0f, mab = 0.0f;
#pragma unroll
        for (int i = 0; i < 8; i++) {
            x[i] = src[lane + 32 * i];
            ss += x[i].x*x[i].x + x[i].y*x[i].y + x[i].z*x[i].z + x[i].w*x[i].w;
            mab = fmaxf(mab, fmaxf(fmaxf(fabsf(x[i].x), fabsf(x[i].y)),
                                   fmaxf(fabsf(x[i].z), fabsf(x[i].w))));
        }
        float tot = warp_sum(ss);
        float m = warp_max(mab);
        if (lane == 0) { g_c2[k] = tot; g_bscale[k] = m * (1.0f/127.0f); }
        float qs = 127.0f / m;
        uint32_t* dst = g_cb_q + (size_t)k * 256;
#pragma unroll
        for (int i = 0; i < 8; i++)
            dst[lane + 32 * i] = quant_pack(x[i], qs);
    } else {
        const int i0 = (b - 2560) * 2048 + tid;
        float4 z = make_float4(0.f, 0.f, 0.f, 0.f);
#pragma unroll
        for (int j = 0; j < 8; j++)
            reinterpret_cast<float4*>(g_sums)[i0 + j * 256] = z;
        if (b == 2560 && tid < K_CB / 4) reinterpret_cast<float4*>(g_counts)[tid] = z;
    }
}

extern __shared__ char dynsmem[];

__device__ __forceinline__ void load_chunk(uint32_t st, int m0, int n0, int ch, int tid) {
    const int c = tid & 7;
    const int r0 = tid >> 3;
    const int koff4 = ch * (KCH/4) + c * 4;
#pragma unroll
    for (int i = 0; i < 4; i++) {
        int r = r0 + i * 32;
        CPA16(st + r * ROW_BYTES + c * 16,
              g_feat_q + (size_t)(m0 + r) * 256 + koff4);
    }
#pragma unroll
    for (int i = 0; i < 4; i++) {
        int r = r0 + i * 32;
        CPA16(st + TILE_BYTES + r * ROW_BYTES + c * 16,
              g_cb_q + (size_t)(n0 + r) * 256 + koff4);
    }
}

__global__ void __launch_bounds__(256, 2) score_imma_kernel() {
    __shared__ float s_c2[BTN];
    __shared__ float s_bs[BTN];

    const int tid = threadIdx.x;
    const int wid = tid >> 5;
    const int lane = tid & 31;
    const int m0 = (blockIdx.x >> 5) * BTM;
    const int n0 = (blockIdx.x & 31) * BTN;
    const uint32_t sbase = s2u(dynsmem);

    const int wm = (wid & 3) * 32;
    const int wn = (wid >> 2) * 64;

    int acc[2][8][4];
#pragma unroll
    for (int i = 0; i < 2; i++)
#pragma unroll
        for (int j = 0; j < 8; j++)
#pragma unroll
            for (int e = 0; e < 4; e++) acc[i][j][e] = 0;

    const int a_row = wm + (lane & 15);
    const int a_un  = (lane >> 4);
    const int b_row = wn + (lane & 7) + ((lane >> 4) << 3);
    const int b_un  = ((lane >> 3) & 1);

    // PDL: grid launches/ramps during prep's tail; data deps start here.
    GRIDDEP_WAIT();

    if (tid < BTN) { s_c2[tid] = g_c2[n0 + tid]; s_bs[tid] = g_bscale[n0 + tid]; }

    load_chunk(sbase, m0, n0, 0, tid);
    CPA_COMMIT();

    for (int ch = 0; ch < NCHUNK; ch++) {
        CPA_WAIT0();
        __syncthreads();
        if (ch + 1 < NCHUNK) {
            load_chunk(sbase + ((ch + 1) & 1) * STAGE_BYTES, m0, n0, ch + 1, tid);
            CPA_COMMIT();
        }
        const uint32_t cur = sbase + (ch & 1) * STAGE_BYTES;

#pragma unroll
        for (int k32 = 0; k32 < 4; k32++) {
            const int au = (k32 * 2 + a_un) * 16;
            const int bu = (k32 * 2 + b_un) * 16;
            uint32_t Ah[2][4], Bh[4][4];
#pragma unroll
            for (int bm = 0; bm < 2; bm++)
                ldsm_x4(cur + (a_row + bm * 16) * ROW_BYTES + au, Ah[bm]);
#pragma unroll
            for (int q = 0; q < 4; q++)
                ldsm_x4(cur + TILE_BYTES + (b_row + q * 16) * ROW_BYTES + bu, Bh[q]);
#pragma unroll
            for (int bm = 0; bm < 2; bm++)
#pragma unroll
                for (int q = 0; q < 4; q++) {
                    imma16832(acc[bm][2*q],   Ah[bm], Bh[q][0], Bh[q][1]);
                    imma16832(acc[bm][2*q+1], Ah[bm], Bh[q][2], Bh[q][3]);
                }
        }
    }

    // epilogue: score = c2 - 2*as*bs*acc; per-row top-2 in this warp's 64 cols
    const int tr = lane & 3;
    const int tq = lane >> 2;
    const int chunk = (n0 + wn) >> 6;
#pragma unroll
    for (int bm = 0; bm < 2; bm++) {
#pragma unroll
        for (int h = 0; h < 2; h++) {
            const int row = m0 + wm + bm * 16 + h * 8 + tq;
            const float as2 = -2.0f * __ldg(&g_ascale[row]);
            unsigned long long k1 = 0xFFFFFFFFFFFFFFFFull, k2 = 0xFFFFFFFFFFFFFFFFull;
#pragma unroll
            for (int nb = 0; nb < 8; nb++) {
#pragma unroll
                for (int e = 0; e < 2; e++) {
                    const int nl = wn + nb * 8 + tr * 2 + e;
                    const float s = fmaf(as2 * s_bs[nl],
                                         (float)acc[bm][nb][h * 2 + e], s_c2[nl]);
                    unsigned long long key =
                        ((unsigned long long)enc_f(s) << 32) | (unsigned)(n0 + nl);
                    if (key < k1) { k2 = k1; k1 = key; }
                    else if (key < k2) { k2 = key; }
                }
            }
#pragma unroll
            for (int o = 1; o < 4; o <<= 1) {
                unsigned long long o1 = __shfl_xor_sync(0xffffffffu, k1, o);
                unsigned long long o2 = __shfl_xor_sync(0xffffffffu, k2, o);
                unsigned long long n1 = (k1 < o1) ? k1 : o1;
                unsigned long long mx = (k1 < o1) ? o1 : k1;
                unsigned long long mn2 = (k2 < o2) ? k2 : o2;
                k1 = n1;
                k2 = (mx < mn2) ? mx : mn2;
            }
            if (tr == 0)
                st_v2u64(g_cand + (size_t)row * 128 + chunk * 2, k1, k2);
        }
    }
}

// fused: one warp per row. PDL: prefetch prep-produced operands, then wait on score.
__global__ void __launch_bounds__(256) resolve_agg_kernel(const float* __restrict__ hs,
                                                          const float* __restrict__ cb,
                                                          float* __restrict__ out_ids) {
    __shared__ int cand[8][40];
    const int tid = threadIdx.x;
    const int wid = tid >> 5;
    const int lane = tid & 31;
    const int row = blockIdx.x * 8 + wid;

    // --- prefetch: depends only on prep_kernel, overlaps score tail ---
    const float as = g_ascale[row];
    const float inv = g_invn[row];
    const uint32_t* qp = g_feat_q + (size_t)row * 256;
    uint32_t qv[8];
#pragma unroll
    for (int i = 0; i < 8; i++) qv[i] = qp[lane + 32 * i];

    GRIDDEP_WAIT();   // score_imma_kernel's g_cand now visible

    const unsigned long long* keys = g_cand + (size_t)row * 128;
    unsigned long long kk[4];
#pragma unroll
    for (int i = 0; i < 2; i++) {
        ulonglong2 v = __ldg(reinterpret_cast<const ulonglong2*>(keys) + lane * 2 + i);
        kk[i * 2] = v.x; kk[i * 2 + 1] = v.y;
    }
    unsigned long long mn = kk[0];
#pragma unroll
    for (int i = 1; i < 4; i++) if (kk[i] < mn) mn = kk[i];
#pragma unroll
    for (int o = 16; o > 0; o >>= 1) {
        unsigned long long om = __shfl_xor_sync(0xffffffffu, mn, o);
        if (om < mn) mn = om;
    }
    const float s1 = dec_f((unsigned)(mn >> 32));
    const float thr = s1 + RESCUE_TAU;

    int base = 0;
#pragma unroll
    for (int i = 0; i < 4; i++) {
        bool fl = dec_f((unsigned)(kk[i] >> 32)) < thr;
        unsigned m = __ballot_sync(0xffffffffu, fl);
        if (fl) {
            int pos = base + __popc(m & ((1u << lane) - 1u));
            if (pos < 40) cand[wid][pos] = (int)(unsigned)(kk[i] & 0xFFFFFFFFull);
        }
        base += __popc(m);
    }
    const int total = (base < 40) ? base : 40;

    int id;
    if (total <= 1) {
        id = (int)(unsigned)(mn & 0xFFFFFFFFull);
    } else {
        __syncwarp();
        const float* fr = hs + (size_t)row * C_DIM;
        float bs = FLT_MAX;
        int bk = 0x7fffffff;
        for (int c = 0; c < total; c++) {
            const int k = cand[wid][c];
            const float* cr = cb + (size_t)k * C_DIM;
            float a = 0.0f;
#pragma unroll 8
            for (int j = 0; j < 32; j++)
                a = fmaf(fr[lane + 32 * j] * inv, cr[lane + 32 * j], a);
#pragma unroll
            for (int o = 16; o > 0; o >>= 1) a += __shfl_xor_sync(0xffffffffu, a, o);
            const float s = fmaf(-2.0f, a, g_c2[k]);
            if (s < bs || (s == bs && k < bk)) { bs = s; bk = k; }
        }
        id = bk;   // warp-uniform
    }

    if (lane == 0) {
        out_ids[row] = (float)id;
        atomicAdd(&g_counts[id], 1.0f);
    }
    float* dst = g_sums + (size_t)id * C_DIM;
#pragma unroll
    for (int i = 0; i < 8; i++) {
        const int e = lane + 32 * i;
        uint32_t u = qv[i];
        float4 f = make_float4(as * (float)((int)(u << 24) >> 24),
                               as * (float)((int)(u << 16) >> 24),
                               as * (float)((int)(u << 8)  >> 24),
                               as * (float)((int)u >> 24));
        red_v4(dst + e * 4, f);
    }
}

// warp-per-cluster EMA + renormalize, 3-pass (low regs): pass1 ||mean||,
// pass2 v = EMA -> overwrite g_sums (dead scratch), pass3 output v*inv2 | cb.
__global__ void __launch_bounds__(128) finalize_kernel(const float* __restrict__ cb,
                                                       float* __restrict__ out) {
    const int wid = threadIdx.x >> 5;
    const int lane = threadIdx.x & 31;
    const int k = blockIdx.x * 4 + wid;

    GRIDDEP_WAIT();   // resolve_agg's g_sums/g_counts now visible

    const float cnt = g_counts[k];
    const float inv_d = 1.0f / fmaxf(cnt, 1.0f);
    float4* sr = reinterpret_cast<float4*>(g_sums) + (size_t)k * C4;
    const float4* cr = reinterpret_cast<const float4*>(cb) + (size_t)k * C4;

    // pass 1: ||mean||
    float ss = 0.0f;
#pragma unroll
    for (int i = 0; i < 8; i++) {
        float4 s = sr[lane + 32 * i];
        float mx = s.x * inv_d, my = s.y * inv_d, mz = s.z * inv_d, mw = s.w * inv_d;
        ss += mx*mx + my*my + mz*mz + mw*mw;
    }
    float inv1 = 1.0f / fmaxf(sqrtf(warp_sum(ss)), EPS);

    // pass 2: v = EMA(c, mean*inv1); store v into g_sums (scratch reuse); ||v||
    float ss2 = 0.0f;
#pragma unroll
    for (int i = 0; i < 8; i++) {
        float4 s = sr[lane + 32 * i];
        float4 c = cr[lane + 32 * i];
        float4 v;
        v.x = MOMENTUM * c.x + (1.0f - MOMENTUM) * ((s.x * inv_d) * inv1);
        v.y = MOMENTUM * c.y + (1.0f - MOMENTUM) * ((s.y * inv_d) * inv1);
        v.z = MOMENTUM * c.z + (1.0f - MOMENTUM) * ((s.z * inv_d) * inv1);
        v.w = MOMENTUM * c.w + (1.0f - MOMENTUM) * ((s.w * inv_d) * inv1);
        ss2 += v.x*v.x + v.y*v.y + v.z*v.z + v.w*v.w;
        sr[lane + 32 * i] = v;
    }
    float inv2 = 1.0f / fmaxf(sqrtf(warp_sum(ss2)), EPS);

    // pass 3: output (L2-hot re-reads)
    float4* outr = reinterpret_cast<float4*>(out) + (size_t)k * C4;
#pragma unroll
    for (int i = 0; i < 8; i++) {
        float4 o;
        if (cnt > 0.0f) {
            float4 v = sr[lane + 32 * i];
            o = make_float4(v.x * inv2, v.y * inv2, v.z * inv2, v.w * inv2);
        } else {
            o = cr[lane + 32 * i];
        }
        outr[lane + 32 * i] = o;
    }
}

// ---------------- launch ----------------
extern "C" void kernel_launch(void* const* d_in, const int* in_sizes, int n_in,
                              void* d_out, int out_size) {
    const float* hs = (const float*)d_in[0];   // (4,4096,1024) f32
    const float* cb = (const float*)d_in[1];   // (4096,1024) f32
    float* out = (float*)d_out;                // [16384 ids][4096*1024 codebook]

    cudaFuncSetAttribute(score_imma_kernel,
                         cudaFuncAttributeMaxDynamicSharedMemorySize, NSTAGE * STAGE_BYTES);

    prep_kernel<<<3072, 256>>>(hs, cb);

    cudaLaunchAttribute attr[1];
    attr[0].id = cudaLaunchAttributeProgrammaticStreamSerialization;
    attr[0].val.programmaticStreamSerializationAllowed = 1;

    {
        cudaLaunchConfig_t cfg = {};
        cfg.gridDim = dim3((N_TOK / BTM) * (K_CB / BTN));
        cfg.blockDim = dim3(256);
        cfg.dynamicSmemBytes = NSTAGE * STAGE_BYTES;
        cfg.attrs = attr;
        cfg.numAttrs = 1;
        cudaLaunchKernelEx(&cfg, score_imma_kernel);
    }
    {
        cudaLaunchConfig_t cfg = {};
        cfg.gridDim = dim3(N_TOK / 8);
        cfg.blockDim = dim3(256);
        cfg.attrs = attr;
        cfg.numAttrs = 1;
        cudaLaunchKernelEx(&cfg, resolve_agg_kernel, hs, cb, out);
    }
    {
        cudaLaunchConfig_t cfg = {};
        cfg.gridDim = dim3(K_CB / 4);
        cfg.blockDim = dim3(128);
        cfg.attrs = attr;
        cfg.numAttrs = 1;
        cudaLaunchKernelEx(&cfg, finalize_kernel, cb, out + N_TOK);
    }
}

// round 17
// speedup vs baseline: 1.0662x; 1.0662x over previous
#include <cuda_runtime.h>
#include <cuda_fp16.h>
#include <float.h>
#include <math.h>
#include <stdint.h>

#define N_TOK 16384
#define C_DIM 1024
#define C4    (C_DIM/4)
#define K_CB  4096
#define MOMENTUM 0.99f
#define EPS 1e-6f

// ---- GEMM tiling (int8) ----
#define BTM 128
#define BTN 128
#define KCH 128
#define NCHUNK (C_DIM/KCH)            // 8
#define ROW_BYTES 144
#define TILE_BYTES (128*ROW_BYTES)    // 18432
#define STAGE_BYTES (2*TILE_BYTES)    // 36864
#define NSTAGE 2                      // 73.7KB -> 2 CTAs/SM
#define RESCUE_TAU 6.0e-3f

// ---------------- device scratch ----------------
__device__ float    g_invn[N_TOK];
__device__ float    g_ascale[N_TOK];
__device__ float    g_bscale[K_CB];
__device__ uint32_t g_feat_q[(size_t)N_TOK*C_DIM/4];
__device__ uint32_t g_cb_q[(size_t)K_CB*C_DIM/4];
__device__ float    g_c2[K_CB];
__device__ float    g_sums[(size_t)K_CB*C_DIM];
__device__ float    g_counts[K_CB];
__device__ unsigned long long g_cand[(size_t)N_TOK*128];

// ---------------- PTX helpers ----------------
__device__ __forceinline__ uint32_t s2u(const void* p) {
    uint32_t a;
    asm("{ .reg .u64 t; cvta.to.shared.u64 t, %1; cvt.u32.u64 %0, t; }" : "=r"(a) : "l"(p));
    return a;
}
#define CPA16(d, s) asm volatile("cp.async.cg.shared.global [%0], [%1], 16;" :: "r"(d), "l"(s))
#define CPA_COMMIT() asm volatile("cp.async.commit_group;" ::: "memory")
#define CPA_WAIT0()  asm volatile("cp.async.wait_group 0;" ::: "memory")
#define GRIDDEP_WAIT() asm volatile("griddepcontrol.wait;" ::: "memory")

__device__ __forceinline__ void ldsm_x4(uint32_t addr, uint32_t* r) {
    asm volatile("ldmatrix.sync.aligned.m8n8.x4.shared.b16 {%0,%1,%2,%3}, [%4];"
                 : "=r"(r[0]), "=r"(r[1]), "=r"(r[2]), "=r"(r[3]) : "r"(addr));
}
__device__ __forceinline__ void imma16832(int* c, const uint32_t* a, uint32_t b0, uint32_t b1) {
    asm volatile("mma.sync.aligned.m16n8k32.row.col.s32.s8.s8.s32 "
                 "{%0,%1,%2,%3}, {%4,%5,%6,%7}, {%8,%9}, {%0,%1,%2,%3};"
                 : "+r"(c[0]), "+r"(c[1]), "+r"(c[2]), "+r"(c[3])
                 : "r"(a[0]), "r"(a[1]), "r"(a[2]), "r"(a[3]), "r"(b0), "r"(b1));
}
__device__ __forceinline__ void red_v4(float* gaddr, float4 v) {
    asm volatile("red.global.add.v4.f32 [%0], {%1,%2,%3,%4};"
                 :: "l"(gaddr), "f"(v.x), "f"(v.y), "f"(v.z), "f"(v.w) : "memory");
}
__device__ __forceinline__ void st_v2u64(unsigned long long* gaddr,
                                         unsigned long long a, unsigned long long b) {
    asm volatile("st.global.v2.u64 [%0], {%1,%2};" :: "l"(gaddr), "l"(a), "l"(b) : "memory");
}

__device__ __forceinline__ unsigned enc_f(float f) {
    unsigned u = __float_as_uint(f);
    return (u & 0x80000000u) ? ~u : (u | 0x80000000u);
}
__device__ __forceinline__ float dec_f(unsigned u) {
    unsigned b = (u & 0x80000000u) ? (u & 0x7FFFFFFFu) : ~u;
    return __uint_as_float(b);
}
__device__ __forceinline__ float warp_sum(float v) {
#pragma unroll
    for (int o = 16; o > 0; o >>= 1) v += __shfl_xor_sync(0xffffffffu, v, o);
    return v;
}
__device__ __forceinline__ float warp_max(float v) {
#pragma unroll
    for (int o = 16; o > 0; o >>= 1) v = fmaxf(v, __shfl_xor_sync(0xffffffffu, v, o));
    return v;
}
__device__ __forceinline__ uint32_t quant_pack(float4 o, float qs) {
    int qx = __float2int_rn(o.x * qs), qy = __float2int_rn(o.y * qs);
    int qz = __float2int_rn(o.z * qs), qw = __float2int_rn(o.w * qs);
    return (qx & 0xFF) | ((qy & 0xFF) << 8) | ((qz & 0xFF) << 16) | ((qw & 0xFF) << 24);
}

// ---------------- prep: warp-per-row ----------------
__global__ void __launch_bounds__(256) prep_kernel(const float* __restrict__ hs,
                                                   const float* __restrict__ cb) {
    const int tid = threadIdx.x;
    const int wid = tid >> 5;
    const int lane = tid & 31;
    const int b = blockIdx.x;

    if (b < 2048) {
        const int row = b * 8 + wid;
        const float4* src = reinterpret_cast<const float4*>(hs) + (size_t)row * C4;
        float4 x[8];
        float ss = 0.0f, mab = 0.0f;
#pragma unroll
        for (int i = 0; i < 8; i++) {
            x[i] = src[lane + 32 * i];
            ss += x[i].x*x[i].x + x[i].y*x[i].y + x[i].z*x[i].z + x[i].w*x[i].w;
            mab = fmaxf(mab, fmaxf(fmaxf(fabsf(x[i].x), fabsf(x[i].y)),
                                   fmaxf(fabsf(x[i].z), fabsf(x[i].w))));
        }
        float nrm = sqrtf(warp_sum(ss));
        float mraw = warp_max(mab);
        float inv = 1.0f / fmaxf(nrm, EPS);
        float m = mraw * inv;
        if (lane == 0) { g_invn[row] = inv; g_ascale[row] = m * (1.0f/127.0f); }
        float qs = 127.0f / m;
        uint32_t* dst = g_feat_q + (size_t)row * 256;
#pragma unroll
        for (int i = 0; i < 8; i++) {
            float4 o = make_float4(x[i].x*inv, x[i].y*inv, x[i].z*inv, x[i].w*inv);
            dst[lane + 32 * i] = quant_pack(o, qs);
        }
    } else if (b < 2560) {
        const int k = (b - 2048) * 8 + wid;
        const float4* src = reinterpret_cast<const float4*>(cb) + (size_t)k * C4;
        float4 x[8];
        float ss = 0.0f, mab = 0.0f;
#pragma unroll
        for (int i = 0; i < 8; i++) {
            x[i] = src[lane + 32 * i];
            ss += x[i].x*x[i].x + x[i].y*x[i].y + x[i].z*x[i].z + x[i].w*x[i].w;
            mab = fmaxf(mab, fmaxf(fmaxf(fabsf(x[i].x), fabsf(x[i].y)),
                                   fmaxf(fabsf(x[i].z), fabsf(x[i].w))));
        }
        float tot = warp_sum(ss);
        float m = warp_max(mab);
        if (lane == 0) { g_c2[k] = tot; g_bscale[k] = m * (1.0f/127.0f); }
        float qs = 127.0f / m;
        uint32_t* dst = g_cb_q + (size_t)k * 256;
#pragma unroll
        for (int i = 0; i < 8; i++)
            dst[lane + 32 * i] = quant_pack(x[i], qs);
    } else {
        const int i0 = (b - 2560) * 2048 + tid;
        float4 z = make_float4(0.f, 0.f, 0.f, 0.f);
#pragma unroll
        for (int j = 0; j < 8; j++)
            reinterpret_cast<float4*>(g_sums)[i0 + j * 256] = z;
        if (b == 2560 && tid < K_CB / 4) reinterpret_cast<float4*>(g_counts)[tid] = z;
    }
}

extern __shared__ char dynsmem[];

__device__ __forceinline__ void load_chunk(uint32_t st, int m0, int n0, int ch, int tid) {
    const int c = tid & 7;
    const int r0 = tid >> 3;
    const int koff4 = ch * (KCH/4) + c * 4;
#pragma unroll
    for (int i = 0; i < 4; i++) {
        int r = r0 + i * 32;
        CPA16(st + r * ROW_BYTES + c * 16,
              g_feat_q + (size_t)(m0 + r) * 256 + koff4);
    }
#pragma unroll
    for (int i = 0; i < 4; i++) {
        int r = r0 + i * 32;
        CPA16(st + TILE_BYTES + r * ROW_BYTES + c * 16,
              g_cb_q + (size_t)(n0 + r) * 256 + koff4);
    }
}

__global__ void __launch_bounds__(256, 2) score_imma_kernel() {
    __shared__ float s_c2[BTN];
    __shared__ float s_bs[BTN];

    const int tid = threadIdx.x;
    const int wid = tid >> 5;
    const int lane = tid & 31;
    const int m0 = (blockIdx.x >> 5) * BTM;
    const int n0 = (blockIdx.x & 31) * BTN;
    const uint32_t sbase = s2u(dynsmem);

    const int wm = (wid & 3) * 32;
    const int wn = (wid >> 2) * 64;

    int acc[2][8][4];
#pragma unroll
    for (int i = 0; i < 2; i++)
#pragma unroll
        for (int j = 0; j < 8; j++)
#pragma unroll
            for (int e = 0; e < 4; e++) acc[i][j][e] = 0;

    const int a_row = wm + (lane & 15);
    const int a_un  = (lane >> 4);
    const int b_row = wn + (lane & 7) + ((lane >> 4) << 3);
    const int b_un  = ((lane >> 3) & 1);

    // PDL: grid launches/ramps during prep's tail; data deps start here.
    GRIDDEP_WAIT();

    // cp.async stream first (bulk), scalar s_c2/s_bs loads overlap behind it
    load_chunk(sbase, m0, n0, 0, tid);
    CPA_COMMIT();
    if (tid < BTN) { s_c2[tid] = g_c2[n0 + tid]; s_bs[tid] = g_bscale[n0 + tid]; }

    for (int ch = 0; ch < NCHUNK; ch++) {
        CPA_WAIT0();
        __syncthreads();
        if (ch + 1 < NCHUNK) {
            load_chunk(sbase + ((ch + 1) & 1) * STAGE_BYTES, m0, n0, ch + 1, tid);
            CPA_COMMIT();
        }
        const uint32_t cur = sbase + (ch & 1) * STAGE_BYTES;

#pragma unroll
        for (int k32 = 0; k32 < 4; k32++) {
            const int au = (k32 * 2 + a_un) * 16;
            const int bu = (k32 * 2 + b_un) * 16;
            uint32_t Ah[2][4], Bh[4][4];
#pragma unroll
            for (int bm = 0; bm < 2; bm++)
                ldsm_x4(cur + (a_row + bm * 16) * ROW_BYTES + au, Ah[bm]);
#pragma unroll
            for (int q = 0; q < 4; q++)
                ldsm_x4(cur + TILE_BYTES + (b_row + q * 16) * ROW_BYTES + bu, Bh[q]);
#pragma unroll
            for (int bm = 0; bm < 2; bm++)
#pragma unroll
                for (int q = 0; q < 4; q++) {
                    imma16832(acc[bm][2*q],   Ah[bm], Bh[q][0], Bh[q][1]);
                    imma16832(acc[bm][2*q+1], Ah[bm], Bh[q][2], Bh[q][3]);
                }
        }
    }

    // epilogue: score = c2 - 2*as*bs*acc; per-row top-2 in this warp's 64 cols
    const int tr = lane & 3;
    const int tq = lane >> 2;
    const int chunk = (n0 + wn) >> 6;
#pragma unroll
    for (int bm = 0; bm < 2; bm++) {
#pragma unroll
        for (int h = 0; h < 2; h++) {
            const int row = m0 + wm + bm * 16 + h * 8 + tq;
            const float as2 = -2.0f * __ldg(&g_ascale[row]);
            unsigned long long k1 = 0xFFFFFFFFFFFFFFFFull, k2 = 0xFFFFFFFFFFFFFFFFull;
#pragma unroll
            for (int nb = 0; nb < 8; nb++) {
#pragma unroll
                for (int e = 0; e < 2; e++) {
                    const int nl = wn + nb * 8 + tr * 2 + e;
                    const float s = fmaf(as2 * s_bs[nl],
                                         (float)acc[bm][nb][h * 2 + e], s_c2[nl]);
                    unsigned long long key =
                        ((unsigned long long)enc_f(s) << 32) | (unsigned)(n0 + nl);
                    if (key < k1) { k2 = k1; k1 = key; }
                    else if (key < k2) { k2 = key; }
                }
            }
#pragma unroll
            for (int o = 1; o < 4; o <<= 1) {
                unsigned long long o1 = __shfl_xor_sync(0xffffffffu, k1, o);
                unsigned long long o2 = __shfl_xor_sync(0xffffffffu, k2, o);
                unsigned long long n1 = (k1 < o1) ? k1 : o1;
                unsigned long long mx = (k1 < o1) ? o1 : k1;
                unsigned long long mn2 = (k2 < o2) ? k2 : o2;
                k1 = n1;
                k2 = (mx < mn2) ? mx : mn2;
            }
            if (tr == 0)
                st_v2u64(g_cand + (size_t)row * 128 + chunk * 2, k1, k2);
        }
    }
}

// fused: one warp per row. PDL: prefetch prep-produced operands, then wait on score.
__global__ void __launch_bounds__(256) resolve_agg_kernel(const float* __restrict__ hs,
                                                          const float* __restrict__ cb,
                                                          float* __restrict__ out_ids) {
    __shared__ int cand[8][40];
    const int tid = threadIdx.x;
    const int wid = tid >> 5;
    const int lane = tid & 31;
    const int row = blockIdx.x * 8 + wid;

    // --- prefetch: depends only on prep_kernel, overlaps score tail ---
    const float as = g_ascale[row];
    const float inv = g_invn[row];
    const uint32_t* qp = g_feat_q + (size_t)row * 256;
    uint32_t qv[8];
#pragma unroll
    for (int i = 0; i < 8; i++) qv[i] = qp[lane + 32 * i];

    GRIDDEP_WAIT();   // score_imma_kernel's g_cand now visible

    const unsigned long long* keys = g_cand + (size_t)row * 128;
    unsigned long long kk[4];
#pragma unroll
    for (int i = 0; i < 2; i++) {
        ulonglong2 v = __ldg(reinterpret_cast<const ulonglong2*>(keys) + lane * 2 + i);
        kk[i * 2] = v.x; kk[i * 2 + 1] = v.y;
    }
    unsigned long long mn = kk[0];
#pragma unroll
    for (int i = 1; i < 4; i++) if (kk[i] < mn) mn = kk[i];
#pragma unroll
    for (int o = 16; o > 0; o >>= 1) {
        unsigned long long om = __shfl_xor_sync(0xffffffffu, mn, o);
        if (om < mn) mn = om;
    }
    const float s1 = dec_f((unsigned)(mn >> 32));
    const float thr = s1 + RESCUE_TAU;

    int base = 0;
#pragma unroll
    for (int i = 0; i < 4; i++) {
        bool fl = dec_f((unsigned)(kk[i] >> 32)) < thr;
        unsigned m = __ballot_sync(0xffffffffu, fl);
        if (fl) {
            int pos = base + __popc(m & ((1u << lane) - 1u));
            if (pos < 40) cand[wid][pos] = (int)(unsigned)(kk[i] & 0xFFFFFFFFull);
        }
        base += __popc(m);
    }
    const int total = (base < 40) ? base : 40;

    int id;
    if (total <= 1) {
        id = (int)(unsigned)(mn & 0xFFFFFFFFull);
    } else {
        __syncwarp();
        const float* fr = hs + (size_t)row * C_DIM;
        float bs = FLT_MAX;
        int bk = 0x7fffffff;
        for (int c = 0; c < total; c++) {
            const int k = cand[wid][c];
            const float* cr = cb + (size_t)k * C_DIM;
            float a = 0.0f;
#pragma unroll 8
            for (int j = 0; j < 32; j++)
                a = fmaf(fr[lane + 32 * j] * inv, cr[lane + 32 * j], a);
#pragma unroll
            for (int o = 16; o > 0; o >>= 1) a += __shfl_xor_sync(0xffffffffu, a, o);
            const float s = fmaf(-2.0f, a, g_c2[k]);
            if (s < bs || (s == bs && k < bk)) { bs = s; bk = k; }
        }
        id = bk;   // warp-uniform
    }

    if (lane == 0) {
        out_ids[row] = (float)id;
        atomicAdd(&g_counts[id], 1.0f);
    }
    float* dst = g_sums + (size_t)id * C_DIM;
#pragma unroll
    for (int i = 0; i < 8; i++) {
        const int e = lane + 32 * i;
        uint32_t u = qv[i];
        float4 f = make_float4(as * (float)((int)(u << 24) >> 24),
                               as * (float)((int)(u << 16) >> 24),
                               as * (float)((int)(u << 8)  >> 24),
                               as * (float)((int)u >> 24));
        red_v4(dst + e * 4, f);
    }
}

// warp-per-cluster EMA + renormalize (R15 version: register-resident, cb prefetch)
__global__ void __launch_bounds__(128) finalize_kernel(const float* __restrict__ cb,
                                                       float* __restrict__ out) {
    const int wid = threadIdx.x >> 5;
    const int lane = threadIdx.x & 31;
    const int k = blockIdx.x * 4 + wid;

    // prefetch codebook row (independent of resolve_agg)
    const float4* cr = reinterpret_cast<const float4*>(cb) + (size_t)k * C4;
    float4 cvec[8];
#pragma unroll
    for (int i = 0; i < 8; i++) cvec[i] = cr[lane + 32 * i];

    GRIDDEP_WAIT();   // resolve_agg's g_sums/g_counts now visible

    const float cnt = g_counts[k];
    const float inv_d = 1.0f / fmaxf(cnt, 1.0f);
    const float4* sr = reinterpret_cast<const float4*>(g_sums) + (size_t)k * C4;
    float4 mvec[8];
    float ss = 0.0f;
#pragma unroll
    for (int i = 0; i < 8; i++) {
        float4 s = sr[lane + 32 * i];
        mvec[i] = make_float4(s.x * inv_d, s.y * inv_d, s.z * inv_d, s.w * inv_d);
        ss += mvec[i].x*mvec[i].x + mvec[i].y*mvec[i].y
            + mvec[i].z*mvec[i].z + mvec[i].w*mvec[i].w;
    }
    float inv1 = 1.0f / fmaxf(sqrtf(warp_sum(ss)), EPS);

    float ss2 = 0.0f;
#pragma unroll
    for (int i = 0; i < 8; i++) {
        mvec[i].x = MOMENTUM * cvec[i].x + (1.0f - MOMENTUM) * (mvec[i].x * inv1);
        mvec[i].y = MOMENTUM * cvec[i].y + (1.0f - MOMENTUM) * (mvec[i].y * inv1);
        mvec[i].z = MOMENTUM * cvec[i].z + (1.0f - MOMENTUM) * (mvec[i].z * inv1);
        mvec[i].w = MOMENTUM * cvec[i].w + (1.0f - MOMENTUM) * (mvec[i].w * inv1);
        ss2 += mvec[i].x*mvec[i].x + mvec[i].y*mvec[i].y
             + mvec[i].z*mvec[i].z + mvec[i].w*mvec[i].w;
    }
    float inv2 = 1.0f / fmaxf(sqrtf(warp_sum(ss2)), EPS);

    float4* outr = reinterpret_cast<float4*>(out) + (size_t)k * C4;
#pragma unroll
    for (int i = 0; i < 8; i++) {
        float4 o;
        if (cnt > 0.0f) {
            o = make_float4(mvec[i].x * inv2, mvec[i].y * inv2,
                            mvec[i].z * inv2, mvec[i].w * inv2);
        } else {
            o = cvec[i];
        }
        outr[lane + 32 * i] = o;
    }
}

// ---------------- launch ----------------
extern "C" void kernel_launch(void* const* d_in, const int* in_sizes, int n_in,
                              void* d_out, int out_size) {
    const float* hs = (const float*)d_in[0];   // (4,4096,1024) f32
    const float* cb = (const float*)d_in[1];   // (4096,1024) f32
    float* out = (float*)d_out;                // [16384 ids][4096*1024 codebook]

    cudaFuncSetAttribute(score_imma_kernel,
                         cudaFuncAttributeMaxDynamicSharedMemorySize, NSTAGE * STAGE_BYTES);

    prep_kernel<<<3072, 256>>>(hs, cb);

    cudaLaunchAttribute attr[1];
    attr[0].id = cudaLaunchAttributeProgrammaticStreamSerialization;
    attr[0].val.programmaticStreamSerializationAllowed = 1;

    {
        cudaLaunchConfig_t cfg = {};
        cfg.gridDim = dim3((N_TOK / BTM) * (K_CB / BTN));
        cfg.blockDim = dim3(256);
        cfg.dynamicSmemBytes = NSTAGE * STAGE_BYTES;
        cfg.attrs = attr;
        cfg.numAttrs = 1;
        cudaLaunchKernelEx(&cfg, score_imma_kernel);
    }
    {
        cudaLaunchConfig_t cfg = {};
        cfg.gridDim = dim3(N_TOK / 8);
        cfg.blockDim = dim3(256);
        cfg.attrs = attr;
        cfg.numAttrs = 1;
        cudaLaunchKernelEx(&cfg, resolve_agg_kernel, hs, cb, out);
    }
    {
        cudaLaunchConfig_t cfg = {};
        cfg.gridDim = dim3(K_CB / 4);
        cfg.blockDim = dim3(128);
        cfg.attrs = attr;
        cfg.numAttrs = 1;
        cudaLaunchKernelEx(&cfg, finalize_kernel, cb, out + N_TOK);
    }
}